// round 15
// baseline (speedup 1.0000x reference)
#include <cuda_runtime.h>
#include <cstdint>
#include <cstddef>

// Problem constants
#define K_B   64
#define K_T   512
#define K_U   512
#define K_G3  1536
#define N_CTA 128
#define N_THR 512

// SMEM layout (bytes): weights 96KB, hred 36KB (12 rows), xred 24KB (2x4 rows), bias, mask
#define RED_OFF   98304
#define XRED_OFF  135168
#define BIAS_OFF  159744
#define MASK_OFF  159872
#define SMEM_TOTAL 163968

// ---------------- device scratch ----------------
__device__ float g_WA[3 * K_U * 1024];            // layer0 [gate][u][k]
__device__ float g_WB[3 * K_U * 1024];            // layer1
__device__ float g_xT[(size_t)K_T * K_B * K_U];   // x blocked [t][kb][b][ki]
__device__ float g_h0[2 * K_B * K_U];             // double-buffered blocked [kb][b][ki]
__device__ float g_h1[2 * K_B * K_U];
__device__ float g_h0n[2 * K_B * K_U];
__device__ unsigned g_arrive[N_CTA];
__device__ unsigned g_release;

// ---------------- init (reset per replay) ----------------
__global__ void gru_init() {
    int i = blockIdx.x * blockDim.x + threadIdx.x;
    if (i < 2 * K_B * K_U) { g_h0[i] = 0.f; g_h1[i] = 0.f; g_h0n[i] = 0.f; }
    if (i < N_CTA) g_arrive[i] = 0u;
    if (i == 0)    g_release = 0u;
}

// ---------------- weight pack: [k][3U] -> [gate][u][k] ----------------
__global__ void gru_pack_weights(const float* __restrict__ W0, const float* __restrict__ U0,
                                 const float* __restrict__ W1, const float* __restrict__ U1) {
    int idx = blockIdx.x * blockDim.x + threadIdx.x;
    if (idx >= 3 * K_U * 1024) return;
    int k = idx & 1023;
    int u = (idx >> 10) & (K_U - 1);
    int g = idx >> 19;
    int col = g * K_U + u;
    g_WA[idx] = (k < 512) ? W0[(size_t)k * K_G3 + col] : U0[(size_t)(k - 512) * K_G3 + col];
    g_WB[idx] = (k < 512) ? W1[(size_t)k * K_G3 + col] : U1[(size_t)(k - 512) * K_G3 + col];
}

// ---------------- x transpose: [b][t][d] -> [t][d/4][b][4] ----------------
__global__ void gru_transpose_x(const float* __restrict__ x) {
    size_t idx = (size_t)blockIdx.x * blockDim.x + threadIdx.x;
    if (idx >= (size_t)K_T * 128 * K_B) return;
    int b  = idx & 63;
    int kb = (int)(idx >> 6) & 127;
    int t  = (int)(idx >> 13);
    float4 v = reinterpret_cast<const float4*>(x)[((size_t)b * K_T + t) * 128 + kb];
    reinterpret_cast<float4*>(g_xT)[idx] = v;
}

__device__ __forceinline__ float sigmoid_f(float x) { return 1.f / (1.f + __expf(-x)); }

// ---------------- primitives ----------------
__device__ __forceinline__ void lds2(uint32_t a, uint64_t& x, uint64_t& y) {
    asm volatile("ld.shared.v2.u64 {%0,%1},[%2];" : "=l"(x), "=l"(y) : "r"(a));
}
__device__ __forceinline__ void ldg2(const void* p, uint64_t& x, uint64_t& y) {
    asm volatile("ld.global.cg.v2.u64 {%0,%1},[%2];" : "=l"(x), "=l"(y) : "l"(p));
}
__device__ __forceinline__ void fma2(uint64_t& d, uint64_t a, uint64_t b) {
    asm volatile("fma.rn.f32x2 %0,%1,%2,%0;" : "+l"(d) : "l"(a), "l"(b));
}
__device__ __forceinline__ float redu1(uint64_t a) {
    float x0, x1;
    asm volatile("mov.b64 {%0,%1},%2;" : "=f"(x0), "=f"(x1) : "l"(a));
    return x0 + x1;
}
__device__ __forceinline__ void sts32(uint32_t a, float v) {
    asm volatile("st.shared.f32 [%0],%1;" :: "r"(a), "f"(v));
}
__device__ __forceinline__ float lds32(uint32_t a) {
    float v;
    asm volatile("ld.shared.f32 %0,[%1];" : "=f"(v) : "r"(a));
    return v;
}
__device__ __forceinline__ unsigned ldsu32(uint32_t a) {
    unsigned v;
    asm volatile("ld.shared.u32 %0,[%1];" : "=r"(v) : "r"(a));
    return v;
}
__device__ __forceinline__ void barsync(int id, int cnt) {
    asm volatile("bar.sync %0,%1;" :: "r"(id), "r"(cnt) : "memory");
}

// FMA body for one 4-k chunk: 2 b x 4 u x 3 gates
#define CHUNK_FMA(C)                                                                     \
    _Pragma("unroll")                                                                    \
    for (int g = 0; g < 3; ++g) {                                                        \
        _Pragma("unroll")                                                                \
        for (int u = 0; u < 4; ++u) {                                                    \
            uint64_t wl, wh;                                                             \
            lds2(wb + (unsigned)(g * 16384 + u * 4096 + (C) * 16), wl, wh);              \
            const int j = g * 4 + u;                                                     \
            fma2(acc[j], v0l, wl);      fma2(acc[j], v0h, wh);                           \
            fma2(acc[12 + j], v1l, wl); fma2(acc[12 + j], v1h, wh);                      \
        }                                                                                \
    }

// 128-k dot: 16 groups of 2 chunks, double-buffered prefetch
__device__ __forceinline__ void dot32(const char* vp, uint32_t wb, uint64_t* acc) {
    uint64_t va[8], vn[8];
    ldg2(vp, va[0], va[1]);           ldg2(vp + 512, va[2], va[3]);
    ldg2(vp + 1024, va[4], va[5]);    ldg2(vp + 1536, va[6], va[7]);
#pragma unroll
    for (int grp = 0; grp < 16; ++grp) {
        if (grp < 15) {
            const char* q = vp + (size_t)(grp + 1) * 2048;
            ldg2(q, vn[0], vn[1]);        ldg2(q + 512, vn[2], vn[3]);
            ldg2(q + 1024, vn[4], vn[5]); ldg2(q + 1536, vn[6], vn[7]);
        }
#pragma unroll
        for (int cc = 0; cc < 2; ++cc) {
            const int c = grp * 2 + cc;
            uint64_t v0l = va[cc * 4], v0h = va[cc * 4 + 1];
            uint64_t v1l = va[cc * 4 + 2], v1h = va[cc * 4 + 3];
            CHUNK_FMA(c)
        }
#pragma unroll
        for (int j = 0; j < 8; ++j) va[j] = vn[j];
    }
}

// write 24 partials to SMEM at base+row
__device__ __forceinline__ void write_partials(uint32_t base, int lane, int row,
                                               const uint64_t* acc) {
#pragma unroll
    for (int bp = 0; bp < 2; ++bp) {
        const int b = lane + bp * 32;
#pragma unroll
        for (int j = 0; j < 12; ++j)
            sts32(base + (unsigned)(((row * 12 + j) * 64 + b) * 4), redu1(acc[bp * 12 + j]));
    }
}

// ---------------- persistent GRU kernel (fuzzy barrier: x-dot hides barrier wait) --------
__global__ void __launch_bounds__(N_THR, 1) gru_main(
    const int* __restrict__ mask,
    const float* __restrict__ b0, const float* __restrict__ b1,
    float* __restrict__ out) {

    extern __shared__ char smem[];
    const uint32_t sbase = (uint32_t)__cvta_generic_to_shared(smem);
    float4* sW4 = reinterpret_cast<float4*>(smem);

    const int tid  = threadIdx.x;
    const int lane = tid & 31;
    const int kh   = tid >> 5;  // warp: 0-3 x-tail, 4-7 A-h0, 8-11 B-h0n, 12-15 B-h1
    const int cta  = blockIdx.x;
    const int u0g  = cta << 2;

    // ---- stage weights into SMEM: [layer][gate][uu][1024] ----
    for (int idx = tid; idx < 6144; idx += N_THR) {
        int i = idx & 255;
        int w = (idx >> 8) & 3;
        int g = (idx >> 10) % 3;
        int layer = idx / 3072;
        const float4* src = reinterpret_cast<const float4*>(layer ? g_WB : g_WA);
        sW4[idx] = src[(size_t)(g * K_U + u0g + w) * 256 + i];
    }
    // ---- stage biases: sBias[layer][u][4] = {bz, br, bi, bh} ----
    if (tid < 32) {
        int layer = tid >> 4, u = (tid >> 2) & 3, q = tid & 3;
        const float* bb = layer ? b1 : b0;
        int uu = u0g + u;
        float v;
        if (q == 0)      v = bb[uu] + bb[K_G3 + uu];
        else if (q == 1) v = bb[K_U + uu] + bb[K_G3 + K_U + uu];
        else if (q == 2) v = bb[2 * K_U + uu];
        else             v = bb[K_G3 + 2 * K_U + uu];
        sts32(sbase + BIAS_OFF + (unsigned)tid * 4u, v);
    }
    // ---- stage mask bits ----
    for (int wg = kh; wg < 1024; wg += 16) {
        int b = wg >> 4, w = wg & 15;
        int mv = mask[(size_t)b * K_T + w * 32 + lane];
        unsigned word = __ballot_sync(0xffffffffu, mv != 0);
        if (lane == 0)
            *reinterpret_cast<unsigned*>(smem + MASK_OFF + wg * 4) = word;
    }
    __syncthreads();

    const uint32_t hred = sbase + RED_OFF;
    const uint32_t xred = sbase + XRED_OFF;

    // ---- prologue: x(0) into xred[0] ----
    if (kh < 4) {
        uint64_t acc[24];
#pragma unroll
        for (int i = 0; i < 24; ++i) acc[i] = 0;
        dot32((const char*)g_xT + (size_t)kh * 32768 + (size_t)lane * 16,
              sbase + (uint32_t)kh * 512u, acc);
        write_partials(xred, lane, kh, acc);
    }
    __syncthreads();

    // finish roles: tid 0..127 A-fin (b = tid>>1, half = tid&1); tid 128..255 B-fin
    const int fth   = (tid < 128) ? tid : tid - 128;
    const int fb    = fth >> 1;
    const int fhalf = fth & 1;

    float2 h0v = make_float2(0.f, 0.f);
    float2 h1v = make_float2(0.f, 0.f);
    float2 prevv = make_float2(0.f, 0.f);
    const int sidx4 = cta * 64;

    for (int r = 0; r <= K_T; ++r) {
        const int p = r & 1, pb = p ^ 1;
        uint64_t acc[24];
#pragma unroll
        for (int i = 0; i < 24; ++i) acc[i] = 0;

        // ======== main h-dots: warps 4-15 ========
        if (kh >= 4 && kh < 8) {
            if (r < K_T) {
                dot32((const char*)g_h0 + (size_t)p * 131072 + (size_t)(kh - 4) * 32768
                      + (size_t)lane * 16, sbase + 2048u + (uint32_t)(kh - 4) * 512u, acc);
                write_partials(hred, lane, kh - 4, acc);
            }
        } else if (kh >= 8 && kh < 12) {
            if (r >= 1) {
                dot32((const char*)g_h0n + (size_t)pb * 131072 + (size_t)(kh - 8) * 32768
                      + (size_t)lane * 16, sbase + 49152u + (uint32_t)(kh - 8) * 512u, acc);
                write_partials(hred, lane, kh - 4, acc);
            }
        } else if (kh >= 12) {
            if (r >= 1) {
                dot32((const char*)g_h1 + (size_t)pb * 131072 + (size_t)(kh - 12) * 32768
                      + (size_t)lane * 16, sbase + 51200u + (uint32_t)(kh - 12) * 512u, acc);
                write_partials(hred, lane, kh - 4, acc);
            }
        }
        __syncthreads();   // S1: hred + xred[r&1] ready

        // ======== finish: A-fin(r) tid<128, B-fin(r-1) tid 128..255 ========
        if (tid < 128) {
            if (r < K_T) {
                const uint32_t xr = xred + (unsigned)(r & 1) * 12288u;
                float lo[6], hi[6];
#pragma unroll
                for (int jj = 0; jj < 6; ++jj) { lo[jj] = 0.f; hi[jj] = 0.f; }
#pragma unroll
                for (int kk = 0; kk < 4; ++kk)
#pragma unroll
                    for (int jj = 0; jj < 6; ++jj) {
                        const int j = (jj & 1) + (jj >> 1) * 4 + fhalf * 2;
                        lo[jj] += lds32(xr + (unsigned)(((kk * 12 + j) * 64 + fb) * 4));
                        hi[jj] += lds32(hred + (unsigned)(((kk * 12 + j) * 64 + fb) * 4));
                    }
                unsigned word = ldsu32(sbase + MASK_OFF + (unsigned)((fb * 16 + (r >> 5)) * 4));
                const bool m = (word >> (r & 31)) & 1u;
                float2 h0n2;
#pragma unroll
                for (int ul = 0; ul < 2; ++ul) {
                    const int u = fhalf * 2 + ul;
                    float bz = lds32(sbase + BIAS_OFF + (unsigned)((u * 4 + 0) * 4));
                    float br = lds32(sbase + BIAS_OFF + (unsigned)((u * 4 + 1) * 4));
                    float bi = lds32(sbase + BIAS_OFF + (unsigned)((u * 4 + 2) * 4));
                    float bh = lds32(sbase + BIAS_OFF + (unsigned)((u * 4 + 3) * 4));
                    float z    = sigmoid_f(lo[ul] + hi[ul] + bz);
                    float rr   = sigmoid_f(lo[2 + ul] + hi[2 + ul] + br);
                    float cand = tanhf(lo[4 + ul] + bi + rr * (hi[4 + ul] + bh));
                    float hp   = (ul == 0) ? h0v.x : h0v.y;
                    float h0n  = z * hp + (1.f - z) * cand;
                    if (ul == 0) { h0n2.x = h0n; h0v.x = m ? h0n : hp; }
                    else         { h0n2.y = h0n; h0v.y = m ? h0n : hp; }
                }
                reinterpret_cast<float2*>(g_h0n)[(p * 8192 + sidx4 + fb) * 2 + fhalf] = h0n2;
                reinterpret_cast<float2*>(g_h0)[((p ^ 1) * 8192 + sidx4 + fb) * 2 + fhalf] = h0v;
            }
        } else if (tid < 256) {
            if (r >= 1) {
                const int t = r - 1;
                float lo[6], hi[6];
#pragma unroll
                for (int jj = 0; jj < 6; ++jj) { lo[jj] = 0.f; hi[jj] = 0.f; }
#pragma unroll
                for (int kk = 0; kk < 4; ++kk)
#pragma unroll
                    for (int jj = 0; jj < 6; ++jj) {
                        const int j = (jj & 1) + (jj >> 1) * 4 + fhalf * 2;
                        lo[jj] += lds32(hred + (unsigned)((((kk + 4) * 12 + j) * 64 + fb) * 4));
                        hi[jj] += lds32(hred + (unsigned)((((kk + 8) * 12 + j) * 64 + fb) * 4));
                    }
                unsigned word = ldsu32(sbase + MASK_OFF + (unsigned)((fb * 16 + (t >> 5)) * 4));
                const bool m = (word >> (t & 31)) & 1u;
#pragma unroll
                for (int ul = 0; ul < 2; ++ul) {
                    const int u = fhalf * 2 + ul;
                    float bz = lds32(sbase + BIAS_OFF + (unsigned)((16 + u * 4 + 0) * 4));
                    float br = lds32(sbase + BIAS_OFF + (unsigned)((16 + u * 4 + 1) * 4));
                    float bi = lds32(sbase + BIAS_OFF + (unsigned)((16 + u * 4 + 2) * 4));
                    float bh = lds32(sbase + BIAS_OFF + (unsigned)((16 + u * 4 + 3) * 4));
                    float z    = sigmoid_f(lo[ul] + hi[ul] + bz);
                    float rr   = sigmoid_f(lo[2 + ul] + hi[2 + ul] + br);
                    float cand = tanhf(lo[4 + ul] + bi + rr * (hi[4 + ul] + bh));
                    float hp   = (ul == 0) ? h1v.x : h1v.y;
                    float h1n  = z * hp + (1.f - z) * cand;
                    if (ul == 0) { h1v.x = m ? h1n : hp; prevv.x = m ? h1n : prevv.x; }
                    else         { h1v.y = m ? h1n : hp; prevv.y = m ? h1n : prevv.y; }
                }
                reinterpret_cast<float2*>(g_h1)[(p * 8192 + sidx4 + fb) * 2 + fhalf] = h1v;
                reinterpret_cast<float2*>(out)[((size_t)fb * K_T + t) * 256 + cta * 2 + fhalf]
                    = prevv;
            }
        }

        if (r == K_T) break;    // no barrier/tail after the last region

        __syncthreads();        // S2: finish writes complete
        if (tid == 0) {
            __threadfence();
            *(volatile unsigned*)&g_arrive[cta] = (unsigned)(r + 1);
        }

        // ---- x-tail: warps 0-3 compute x(r+1) during barrier wait ----
        if (kh < 4) {
            if (r < K_T - 1) {
                uint64_t xacc[24];
#pragma unroll
                for (int i = 0; i < 24; ++i) xacc[i] = 0;
                dot32((const char*)g_xT + (size_t)(r + 1) * 131072 + (size_t)kh * 32768
                      + (size_t)lane * 16, sbase + (uint32_t)kh * 512u, xacc);
                write_partials(xred + (unsigned)((r + 1) & 1) * 12288u, lane, kh, xacc);
            }
        } else if (cta == 0 && tid >= 128 && tid < 256) {
            // CTA0 pollers: warps 4-7
            while (*(volatile unsigned*)&g_arrive[tid - 128] < (unsigned)(r + 1)) { }
            barsync(1, 128);
            if (tid == 128) {
                __threadfence();
                *(volatile unsigned*)&g_release = (unsigned)(r + 1);
            }
        } else if (cta != 0 && tid == 128) {
            while (*(volatile unsigned*)&g_release < (unsigned)(r + 1)) { }
            __threadfence();
        }
        __syncthreads();        // S3: barrier released + x(r+1) staged
    }

    // finals: (output, h0f, h1f) in d_out (float2 units)
    const size_t fin2 = (size_t)K_B * K_T * 256;
    if (tid < 128)
        reinterpret_cast<float2*>(out)[fin2 + (size_t)fb * 256 + cta * 2 + fhalf] = h0v;
    else if (tid < 256)
        reinterpret_cast<float2*>(out)[fin2 + 64 * 256 + (size_t)fb * 256 + cta * 2 + fhalf] = h1v;
}

// ---------------- launch ----------------
extern "C" void kernel_launch(void* const* d_in, const int* in_sizes, int n_in,
                              void* d_out, int out_size) {
    (void)in_sizes; (void)n_in; (void)out_size;
    const float* x    = (const float*)d_in[0];
    const int*   mask = (const int*)d_in[1];
    const float* W0   = (const float*)d_in[2];
    const float* U0   = (const float*)d_in[3];
    const float* b0   = (const float*)d_in[4];
    const float* W1   = (const float*)d_in[5];
    const float* U1   = (const float*)d_in[6];
    const float* b1   = (const float*)d_in[7];
    float*       out  = (float*)d_out;

    cudaFuncSetAttribute(gru_main, cudaFuncAttributeMaxDynamicSharedMemorySize, SMEM_TOTAL);

    gru_init<<<(2 * K_B * K_U + 255) / 256, 256>>>();
    gru_pack_weights<<<(3 * K_U * 1024 + 255) / 256, 256>>>(W0, U0, W1, U1);
    {
        size_t n4 = (size_t)K_T * 128 * K_B;
        gru_transpose_x<<<(unsigned)((n4 + 255) / 256), 256>>>(x);
    }
    gru_main<<<N_CTA, N_THR, SMEM_TOTAL>>>(mask, b0, b1, out);
}

// round 16
// speedup vs baseline: 1.0774x; 1.0774x over previous
#include <cuda_runtime.h>
#include <cstdint>
#include <cstddef>

// Problem constants
#define K_B   64
#define K_T   512
#define K_U   512
#define K_G3  1536
#define N_CTA 128
#define N_THR 512

// SMEM layout (bytes): weights 96KB, partials 48KB (16 rows), bias, mask bits
#define RED_OFF   98304
#define BIAS_OFF  147456
#define MASK_OFF  147584
#define SMEM_TOTAL 151680

// ---------------- device scratch ----------------
__device__ float g_WA[3 * K_U * 1024];            // layer0 [gate][u][k]
__device__ float g_WB[3 * K_U * 1024];            // layer1
__device__ float g_xT[(size_t)K_T * K_B * K_U];   // x blocked [t][kb][b][ki]
__device__ float g_h0[2 * K_B * K_U];             // double-buffered blocked [kb][b][ki]
__device__ float g_h1[2 * K_B * K_U];
__device__ float g_h0n[2 * K_B * K_U];
__device__ unsigned g_arrive[N_CTA];
__device__ unsigned g_release;

// ---------------- init (reset per replay) ----------------
__global__ void gru_init() {
    int i = blockIdx.x * blockDim.x + threadIdx.x;
    if (i < 2 * K_B * K_U) { g_h0[i] = 0.f; g_h1[i] = 0.f; g_h0n[i] = 0.f; }
    if (i < N_CTA) g_arrive[i] = 0u;
    if (i == 0)    g_release = 0u;
}

// ---------------- weight pack: [k][3U] -> [gate][u][k] ----------------
__global__ void gru_pack_weights(const float* __restrict__ W0, const float* __restrict__ U0,
                                 const float* __restrict__ W1, const float* __restrict__ U1) {
    int idx = blockIdx.x * blockDim.x + threadIdx.x;
    if (idx >= 3 * K_U * 1024) return;
    int k = idx & 1023;
    int u = (idx >> 10) & (K_U - 1);
    int g = idx >> 19;
    int col = g * K_U + u;
    g_WA[idx] = (k < 512) ? W0[(size_t)k * K_G3 + col] : U0[(size_t)(k - 512) * K_G3 + col];
    g_WB[idx] = (k < 512) ? W1[(size_t)k * K_G3 + col] : U1[(size_t)(k - 512) * K_G3 + col];
}

// ---------------- x transpose: [b][t][d] -> [t][d/4][b][4] ----------------
__global__ void gru_transpose_x(const float* __restrict__ x) {
    size_t idx = (size_t)blockIdx.x * blockDim.x + threadIdx.x;
    if (idx >= (size_t)K_T * 128 * K_B) return;
    int b  = idx & 63;
    int kb = (int)(idx >> 6) & 127;
    int t  = (int)(idx >> 13);
    float4 v = reinterpret_cast<const float4*>(x)[((size_t)b * K_T + t) * 128 + kb];
    reinterpret_cast<float4*>(g_xT)[idx] = v;
}

// ---------------- R10 grid barrier (CTA0 aggregates) ----------------
__device__ __forceinline__ void grid_barrier(unsigned step) {
    __syncthreads();
    if (threadIdx.x == 0) {
        __threadfence();
        *(volatile unsigned*)&g_arrive[blockIdx.x] = step;
    }
    if (blockIdx.x == 0) {
        if (threadIdx.x < N_CTA)
            while (*(volatile unsigned*)&g_arrive[threadIdx.x] < step) { }
        __syncthreads();
        if (threadIdx.x == 0) {
            __threadfence();
            *(volatile unsigned*)&g_release = step;
        }
    } else {
        if (threadIdx.x == 0) {
            while (*(volatile unsigned*)&g_release < step) { }
            __threadfence();
        }
    }
    __syncthreads();
}

__device__ __forceinline__ float sigmoid_f(float x) { return 1.f / (1.f + __expf(-x)); }

// ---------------- primitives ----------------
__device__ __forceinline__ void lds2(uint32_t a, uint64_t& x, uint64_t& y) {
    asm volatile("ld.shared.v2.u64 {%0,%1},[%2];" : "=l"(x), "=l"(y) : "r"(a));
}
__device__ __forceinline__ void ldg2(const void* p, uint64_t& x, uint64_t& y) {
    asm volatile("ld.global.cg.v2.u64 {%0,%1},[%2];" : "=l"(x), "=l"(y) : "l"(p));
}
__device__ __forceinline__ void fma2(uint64_t& d, uint64_t a, uint64_t b) {
    asm volatile("fma.rn.f32x2 %0,%1,%2,%0;" : "+l"(d) : "l"(a), "l"(b));
}
__device__ __forceinline__ float redu1(uint64_t a) {
    float x0, x1;
    asm volatile("mov.b64 {%0,%1},%2;" : "=f"(x0), "=f"(x1) : "l"(a));
    return x0 + x1;
}
__device__ __forceinline__ void sts32(uint32_t a, float v) {
    asm volatile("st.shared.f32 [%0],%1;" :: "r"(a), "f"(v));
}
__device__ __forceinline__ float lds32(uint32_t a) {
    float v;
    asm volatile("ld.shared.f32 %0,[%1];" : "=f"(v) : "r"(a));
    return v;
}
__device__ __forceinline__ unsigned ldsu32(uint32_t a) {
    unsigned v;
    asm volatile("ld.shared.u32 %0,[%1];" : "=r"(v) : "r"(a));
    return v;
}

// FMA body for one 4-k chunk: 2 b x 4 u x 3 gates
#define CHUNK_FMA(C)                                                                     \
    _Pragma("unroll")                                                                    \
    for (int g = 0; g < 3; ++g) {                                                        \
        _Pragma("unroll")                                                                \
        for (int u = 0; u < 4; ++u) {                                                    \
            uint64_t wl, wh;                                                             \
            lds2(wb + (unsigned)(g * 16384 + u * 4096 + (C) * 16), wl, wh);              \
            const int j = g * 4 + u;                                                     \
            fma2(acc[j], v0l, wl);      fma2(acc[j], v0h, wh);                           \
            fma2(acc[12 + j], v1l, wl); fma2(acc[12 + j], v1h, wh);                      \
        }                                                                                \
    }

// 128-k dot: 32 chunks, DEPTH-4 chunk-granular prefetch ring (16 u64 buffers,
// same register footprint as the R13 double-buffer, but distance-3 latency cover)
__device__ __forceinline__ void dot32(const char* vp, uint32_t wb, uint64_t* acc) {
    uint64_t vb0[4], vb1[4], vb2[4], vb3[4];
    ldg2(vp, vb0[0], vb0[1]);           ldg2(vp + 512, vb0[2], vb0[3]);
    ldg2(vp + 1024, vb1[0], vb1[1]);    ldg2(vp + 1536, vb1[2], vb1[3]);
    ldg2(vp + 2048, vb2[0], vb2[1]);    ldg2(vp + 2560, vb2[2], vb2[3]);
#pragma unroll
    for (int c = 0; c < 32; ++c) {
        uint64_t* cur = ((c & 3) == 0) ? vb0 : ((c & 3) == 1) ? vb1
                      : ((c & 3) == 2) ? vb2 : vb3;
        if (c < 29) {
            uint64_t* nxt = (((c + 3) & 3) == 0) ? vb0 : (((c + 3) & 3) == 1) ? vb1
                          : (((c + 3) & 3) == 2) ? vb2 : vb3;
            const char* q = vp + (size_t)(c + 3) * 1024;
            ldg2(q, nxt[0], nxt[1]);
            ldg2(q + 512, nxt[2], nxt[3]);
        }
        uint64_t v0l = cur[0], v0h = cur[1], v1l = cur[2], v1h = cur[3];
        CHUNK_FMA(c)
    }
}

// write 24 partials to SMEM red[row][j][b]
__device__ __forceinline__ void write_partials(uint32_t rbase, int lane, int row,
                                               const uint64_t* acc) {
#pragma unroll
    for (int bp = 0; bp < 2; ++bp) {
        const int b = lane + bp * 32;
#pragma unroll
        for (int j = 0; j < 12; ++j)
            sts32(rbase + (unsigned)(((row * 12 + j) * 64 + b) * 4), redu1(acc[bp * 12 + j]));
    }
}

// ---------------- persistent GRU kernel (R13 pipeline + deeper v prefetch) ----------
__global__ void __launch_bounds__(N_THR, 1) gru_main(
    const int* __restrict__ mask,
    const float* __restrict__ b0, const float* __restrict__ b1,
    float* __restrict__ out) {

    extern __shared__ char smem[];
    const uint32_t sbase = (uint32_t)__cvta_generic_to_shared(smem);
    float4* sW4 = reinterpret_cast<float4*>(smem);

    const int tid  = threadIdx.x;
    const int lane = tid & 31;
    const int kh   = tid >> 5;              // warp id: 0..7 A-role, 8..15 B-role
    const int cta  = blockIdx.x;
    const int u0g  = cta << 2;

    // ---- stage weights into SMEM: [layer][gate][uu][1024] ----
    for (int idx = tid; idx < 6144; idx += N_THR) {
        int i = idx & 255;
        int w = (idx >> 8) & 3;
        int g = (idx >> 10) % 3;
        int layer = idx / 3072;
        const float4* src = reinterpret_cast<const float4*>(layer ? g_WB : g_WA);
        sW4[idx] = src[(size_t)(g * K_U + u0g + w) * 256 + i];
    }
    // ---- stage biases: sBias[layer][u][4] = {bz, br, bi, bh} ----
    if (tid < 32) {
        int layer = tid >> 4, u = (tid >> 2) & 3, q = tid & 3;
        const float* bb = layer ? b1 : b0;
        int uu = u0g + u;
        float v;
        if (q == 0)      v = bb[uu] + bb[K_G3 + uu];
        else if (q == 1) v = bb[K_U + uu] + bb[K_G3 + K_U + uu];
        else if (q == 2) v = bb[2 * K_U + uu];
        else             v = bb[K_G3 + 2 * K_U + uu];
        sts32(sbase + BIAS_OFF + (unsigned)tid * 4u, v);
    }
    // ---- stage mask as bit-words: smask[b*16 + w] covers t in [32w, 32w+32) ----
    for (int wg = kh; wg < 1024; wg += 16) {
        int b = wg >> 4, w = wg & 15;
        int mv = mask[(size_t)b * K_T + w * 32 + lane];
        unsigned word = __ballot_sync(0xffffffffu, mv != 0);
        if (lane == 0)
            *reinterpret_cast<unsigned*>(smem + MASK_OFF + wg * 4) = word;
    }
    __syncthreads();

    const uint32_t rbase = sbase + RED_OFF;

    // finish roles: tid 0..127 => A-fin (b = tid>>1, half = tid&1); tid 128..255 => B-fin
    const int fth   = (tid < 128) ? tid : tid - 128;
    const int fb    = fth >> 1;
    const int fhalf = fth & 1;

    float2 h0v = make_float2(0.f, 0.f);     // A-fin threads
    float2 h1v = make_float2(0.f, 0.f);     // B-fin threads
    float2 prevv = make_float2(0.f, 0.f);
    const int sidx4 = cta * 64;

    for (int r = 0; r <= K_T; ++r) {
        const int p = r & 1, pb = p ^ 1;
        uint64_t acc[24];
#pragma unroll
        for (int i = 0; i < 24; ++i) acc[i] = 0;

        // ======== dots: A(r) on warps 0-7, B(r-1) on warps 8-15 ========
        if (kh < 8) {
            if (r < K_T) {
                const char* vp = (kh < 4)
                    ? (const char*)g_xT + (size_t)r * 131072 + (size_t)kh * 32768
                      + (size_t)lane * 16
                    : (const char*)g_h0 + (size_t)p * 131072 + (size_t)(kh - 4) * 32768
                      + (size_t)lane * 16;
                const uint32_t wb = (kh < 4) ? (sbase + (uint32_t)kh * 512u)
                                             : (sbase + 2048u + (uint32_t)(kh - 4) * 512u);
                dot32(vp, wb, acc);
                write_partials(rbase, lane, kh, acc);
            }
        } else {
            if (r >= 1) {
                const int kb = kh - 8;
                const char* vp = (kb < 4)
                    ? (const char*)g_h0n + (size_t)pb * 131072 + (size_t)kb * 32768
                      + (size_t)lane * 16
                    : (const char*)g_h1 + (size_t)pb * 131072 + (size_t)(kb - 4) * 32768
                      + (size_t)lane * 16;
                const uint32_t wb = (kb < 4) ? (sbase + 49152u + (uint32_t)kb * 512u)
                                             : (sbase + 51200u + (uint32_t)(kb - 4) * 512u);
                dot32(vp, wb, acc);
                write_partials(rbase, lane, kh, acc);
            }
        }
        __syncthreads();

        // ======== finish: A-fin(r) tid<128, B-fin(r-1) tid 128..255 ========
        if (tid < 128) {
            if (r < K_T) {
                float lo[6], hi[6];
#pragma unroll
                for (int jj = 0; jj < 6; ++jj) { lo[jj] = 0.f; hi[jj] = 0.f; }
#pragma unroll
                for (int kk = 0; kk < 4; ++kk)
#pragma unroll
                    for (int jj = 0; jj < 6; ++jj) {
                        const int j = (jj & 1) + (jj >> 1) * 4 + fhalf * 2;
                        lo[jj] += lds32(rbase + (unsigned)(((kk * 12 + j) * 64 + fb) * 4));
                        hi[jj] += lds32(rbase + (unsigned)((((kk + 4) * 12 + j) * 64 + fb) * 4));
                    }
                unsigned word = ldsu32(sbase + MASK_OFF + (unsigned)((fb * 16 + (r >> 5)) * 4));
                const bool m = (word >> (r & 31)) & 1u;
                float2 h0n2;
#pragma unroll
                for (int ul = 0; ul < 2; ++ul) {
                    const int u = fhalf * 2 + ul;
                    float bz = lds32(sbase + BIAS_OFF + (unsigned)((u * 4 + 0) * 4));
                    float br = lds32(sbase + BIAS_OFF + (unsigned)((u * 4 + 1) * 4));
                    float bi = lds32(sbase + BIAS_OFF + (unsigned)((u * 4 + 2) * 4));
                    float bh = lds32(sbase + BIAS_OFF + (unsigned)((u * 4 + 3) * 4));
                    float z    = sigmoid_f(lo[ul] + hi[ul] + bz);
                    float rr   = sigmoid_f(lo[2 + ul] + hi[2 + ul] + br);
                    float cand = tanhf(lo[4 + ul] + bi + rr * (hi[4 + ul] + bh));
                    float hp   = (ul == 0) ? h0v.x : h0v.y;
                    float h0n  = z * hp + (1.f - z) * cand;
                    if (ul == 0) { h0n2.x = h0n; h0v.x = m ? h0n : hp; }
                    else         { h0n2.y = h0n; h0v.y = m ? h0n : hp; }
                }
                reinterpret_cast<float2*>(g_h0n)[(p * 8192 + sidx4 + fb) * 2 + fhalf] = h0n2;
                reinterpret_cast<float2*>(g_h0)[((p ^ 1) * 8192 + sidx4 + fb) * 2 + fhalf] = h0v;
            }
        } else if (tid < 256) {
            if (r >= 1) {
                const int t = r - 1;
                float lo[6], hi[6];
#pragma unroll
                for (int jj = 0; jj < 6; ++jj) { lo[jj] = 0.f; hi[jj] = 0.f; }
#pragma unroll
                for (int kk = 0; kk < 4; ++kk)
#pragma unroll
                    for (int jj = 0; jj < 6; ++jj) {
                        const int j = (jj & 1) + (jj >> 1) * 4 + fhalf * 2;
                        lo[jj] += lds32(rbase + (unsigned)((((kk + 8) * 12 + j) * 64 + fb) * 4));
                        hi[jj] += lds32(rbase + (unsigned)((((kk + 12) * 12 + j) * 64 + fb) * 4));
                    }
                unsigned word = ldsu32(sbase + MASK_OFF + (unsigned)((fb * 16 + (t >> 5)) * 4));
                const bool m = (word >> (t & 31)) & 1u;
#pragma unroll
                for (int ul = 0; ul < 2; ++ul) {
                    const int u = fhalf * 2 + ul;
                    float bz = lds32(sbase + BIAS_OFF + (unsigned)((16 + u * 4 + 0) * 4));
                    float br = lds32(sbase + BIAS_OFF + (unsigned)((16 + u * 4 + 1) * 4));
                    float bi = lds32(sbase + BIAS_OFF + (unsigned)((16 + u * 4 + 2) * 4));
                    float bh = lds32(sbase + BIAS_OFF + (unsigned)((16 + u * 4 + 3) * 4));
                    float z    = sigmoid_f(lo[ul] + hi[ul] + bz);
                    float rr   = sigmoid_f(lo[2 + ul] + hi[2 + ul] + br);
                    float cand = tanhf(lo[4 + ul] + bi + rr * (hi[4 + ul] + bh));
                    float hp   = (ul == 0) ? h1v.x : h1v.y;
                    float h1n  = z * hp + (1.f - z) * cand;
                    if (ul == 0) { h1v.x = m ? h1n : hp; prevv.x = m ? h1n : prevv.x; }
                    else         { h1v.y = m ? h1n : hp; prevv.y = m ? h1n : prevv.y; }
                }
                reinterpret_cast<float2*>(g_h1)[(p * 8192 + sidx4 + fb) * 2 + fhalf] = h1v;
                reinterpret_cast<float2*>(out)[((size_t)fb * K_T + t) * 256 + cta * 2 + fhalf]
                    = prevv;
            }
        }

        if (r < K_T) grid_barrier((unsigned)(r + 1));
    }

    // finals: (output, h0f, h1f) in d_out (float2 units)
    const size_t fin2 = (size_t)K_B * K_T * 256;
    if (tid < 128)
        reinterpret_cast<float2*>(out)[fin2 + (size_t)fb * 256 + cta * 2 + fhalf] = h0v;
    else if (tid < 256)
        reinterpret_cast<float2*>(out)[fin2 + 64 * 256 + (size_t)fb * 256 + cta * 2 + fhalf] = h1v;
}

// ---------------- launch ----------------
extern "C" void kernel_launch(void* const* d_in, const int* in_sizes, int n_in,
                              void* d_out, int out_size) {
    (void)in_sizes; (void)n_in; (void)out_size;
    const float* x    = (const float*)d_in[0];
    const int*   mask = (const int*)d_in[1];
    const float* W0   = (const float*)d_in[2];
    const float* U0   = (const float*)d_in[3];
    const float* b0   = (const float*)d_in[4];
    const float* W1   = (const float*)d_in[5];
    const float* U1   = (const float*)d_in[6];
    const float* b1   = (const float*)d_in[7];
    float*       out  = (float*)d_out;

    cudaFuncSetAttribute(gru_main, cudaFuncAttributeMaxDynamicSharedMemorySize, SMEM_TOTAL);

    gru_init<<<(2 * K_B * K_U + 255) / 256, 256>>>();
    gru_pack_weights<<<(3 * K_U * 1024 + 255) / 256, 256>>>(W0, U0, W1, U1);
    {
        size_t n4 = (size_t)K_T * 128 * K_B;
        gru_transpose_x<<<(unsigned)((n4 + 255) / 256), 256>>>(x);
    }
    gru_main<<<N_CTA, N_THR, SMEM_TOTAL>>>(mask, b0, b1, out);
}

// round 17
// speedup vs baseline: 1.8046x; 1.6749x over previous
#include <cuda_runtime.h>
#include <cstdint>
#include <cstddef>

// Problem constants
#define K_B   64
#define K_T   512
#define K_U   512
#define K_G3  1536
#define N_CTA 128
#define N_THR 512

// SMEM layout (bytes): weights 96KB, partials 48KB (16 rows), bias, mask bits
#define RED_OFF   98304
#define BIAS_OFF  147456
#define MASK_OFF  147584
#define SMEM_TOTAL 151680

// ---------------- device scratch ----------------
__device__ float g_WA[3 * K_U * 1024];            // layer0 [gate][u][k]
__device__ float g_WB[3 * K_U * 1024];            // layer1
__device__ float g_xT[(size_t)K_T * K_B * K_U];   // x blocked [t][kb][b][ki]
__device__ float g_h0[2 * K_B * K_U];             // double-buffered blocked [kb][b][ki]
__device__ float g_h1[2 * K_B * K_U];
__device__ float g_h0n[2 * K_B * K_U];
__device__ unsigned g_count;                      // monotone barrier counter

// ---------------- init (reset per replay) ----------------
__global__ void gru_init() {
    int i = blockIdx.x * blockDim.x + threadIdx.x;
    if (i < 2 * K_B * K_U) { g_h0[i] = 0.f; g_h1[i] = 0.f; g_h0n[i] = 0.f; }
    if (i == 0) g_count = 0u;
}

// ---------------- weight pack: [k][3U] -> [gate][u][k] ----------------
__global__ void gru_pack_weights(const float* __restrict__ W0, const float* __restrict__ U0,
                                 const float* __restrict__ W1, const float* __restrict__ U1) {
    int idx = blockIdx.x * blockDim.x + threadIdx.x;
    if (idx >= 3 * K_U * 1024) return;
    int k = idx & 1023;
    int u = (idx >> 10) & (K_U - 1);
    int g = idx >> 19;
    int col = g * K_U + u;
    g_WA[idx] = (k < 512) ? W0[(size_t)k * K_G3 + col] : U0[(size_t)(k - 512) * K_G3 + col];
    g_WB[idx] = (k < 512) ? W1[(size_t)k * K_G3 + col] : U1[(size_t)(k - 512) * K_G3 + col];
}

// ---------------- x transpose: [b][t][d] -> [t][d/4][b][4] ----------------
__global__ void gru_transpose_x(const float* __restrict__ x) {
    size_t idx = (size_t)blockIdx.x * blockDim.x + threadIdx.x;
    if (idx >= (size_t)K_T * 128 * K_B) return;
    int b  = idx & 63;
    int kb = (int)(idx >> 6) & 127;
    int t  = (int)(idx >> 13);
    float4 v = reinterpret_cast<const float4*>(x)[((size_t)b * K_T + t) * 128 + kb];
    reinterpret_cast<float4*>(g_xT)[idx] = v;
}

// ---------------- symmetric monotone-counter grid barrier ----------------
__device__ __forceinline__ void grid_barrier(unsigned step) {
    __syncthreads();
    if (threadIdx.x == 0) {
        __threadfence();
        atomicAdd(&g_count, 1u);
        const unsigned target = step * (unsigned)N_CTA;
        while (*(volatile unsigned*)&g_count < target) { }
        __threadfence();
    }
    __syncthreads();
}

__device__ __forceinline__ float sigmoid_f(float x) { return 1.f / (1.f + __expf(-x)); }

// ---------------- primitives ----------------
__device__ __forceinline__ void lds2(uint32_t a, uint64_t& x, uint64_t& y) {
    asm volatile("ld.shared.v2.u64 {%0,%1},[%2];" : "=l"(x), "=l"(y) : "r"(a));
}
__device__ __forceinline__ void ldg2(const void* p, uint64_t& x, uint64_t& y) {
    asm volatile("ld.global.cg.v2.u64 {%0,%1},[%2];" : "=l"(x), "=l"(y) : "l"(p));
}
__device__ __forceinline__ void fma2(uint64_t& d, uint64_t a, uint64_t b) {
    asm volatile("fma.rn.f32x2 %0,%1,%2,%0;" : "+l"(d) : "l"(a), "l"(b));
}
__device__ __forceinline__ float redu1(uint64_t a) {
    float x0, x1;
    asm volatile("mov.b64 {%0,%1},%2;" : "=f"(x0), "=f"(x1) : "l"(a));
    return x0 + x1;
}
__device__ __forceinline__ void sts32(uint32_t a, float v) {
    asm volatile("st.shared.f32 [%0],%1;" :: "r"(a), "f"(v));
}
__device__ __forceinline__ float lds32(uint32_t a) {
    float v;
    asm volatile("ld.shared.f32 %0,[%1];" : "=f"(v) : "r"(a));
    return v;
}
__device__ __forceinline__ unsigned ldsu32(uint32_t a) {
    unsigned v;
    asm volatile("ld.shared.u32 %0,[%1];" : "=r"(v) : "r"(a));
    return v;
}

// FMA body for one 4-k chunk: 2 b x 4 u x 3 gates
#define CHUNK_FMA(C)                                                                     \
    _Pragma("unroll")                                                                    \
    for (int g = 0; g < 3; ++g) {                                                        \
        _Pragma("unroll")                                                                \
        for (int u = 0; u < 4; ++u) {                                                    \
            uint64_t wl, wh;                                                             \
            lds2(wb + (unsigned)(g * 16384 + u * 4096 + (C) * 16), wl, wh);              \
            const int j = g * 4 + u;                                                     \
            fma2(acc[j], v0l, wl);      fma2(acc[j], v0h, wh);                           \
            fma2(acc[12 + j], v1l, wl); fma2(acc[12 + j], v1h, wh);                      \
        }                                                                                \
    }

// 128-k dot: 16 groups of 2 chunks, R13 double-buffered prefetch (DO NOT TOUCH)
__device__ __forceinline__ void dot32(const char* vp, uint32_t wb, uint64_t* acc) {
    uint64_t va[8], vn[8];
    ldg2(vp, va[0], va[1]);           ldg2(vp + 512, va[2], va[3]);
    ldg2(vp + 1024, va[4], va[5]);    ldg2(vp + 1536, va[6], va[7]);
#pragma unroll
    for (int grp = 0; grp < 16; ++grp) {
        if (grp < 15) {
            const char* q = vp + (size_t)(grp + 1) * 2048;
            ldg2(q, vn[0], vn[1]);        ldg2(q + 512, vn[2], vn[3]);
            ldg2(q + 1024, vn[4], vn[5]); ldg2(q + 1536, vn[6], vn[7]);
        }
#pragma unroll
        for (int cc = 0; cc < 2; ++cc) {
            const int c = grp * 2 + cc;
            uint64_t v0l = va[cc * 4], v0h = va[cc * 4 + 1];
            uint64_t v1l = va[cc * 4 + 2], v1h = va[cc * 4 + 3];
            CHUNK_FMA(c)
        }
#pragma unroll
        for (int j = 0; j < 8; ++j) va[j] = vn[j];
    }
}

// write 24 partials to SMEM red[row][j][b]
__device__ __forceinline__ void write_partials(uint32_t rbase, int lane, int row,
                                               const uint64_t* acc) {
#pragma unroll
    for (int bp = 0; bp < 2; ++bp) {
        const int b = lane + bp * 32;
#pragma unroll
        for (int j = 0; j < 12; ++j)
            sts32(rbase + (unsigned)(((row * 12 + j) * 64 + b) * 4), redu1(acc[bp * 12 + j]));
    }
}

// ---------------- persistent GRU kernel (R13 pipeline + symmetric barrier) ----------
__global__ void __launch_bounds__(N_THR, 1) gru_main(
    const int* __restrict__ mask,
    const float* __restrict__ b0, const float* __restrict__ b1,
    float* __restrict__ out) {

    extern __shared__ char smem[];
    const uint32_t sbase = (uint32_t)__cvta_generic_to_shared(smem);
    float4* sW4 = reinterpret_cast<float4*>(smem);

    const int tid  = threadIdx.x;
    const int lane = tid & 31;
    const int kh   = tid >> 5;              // warp id: 0..7 A-role, 8..15 B-role
    const int cta  = blockIdx.x;
    const int u0g  = cta << 2;

    // ---- stage weights into SMEM: [layer][gate][uu][1024] ----
    for (int idx = tid; idx < 6144; idx += N_THR) {
        int i = idx & 255;
        int w = (idx >> 8) & 3;
        int g = (idx >> 10) % 3;
        int layer = idx / 3072;
        const float4* src = reinterpret_cast<const float4*>(layer ? g_WB : g_WA);
        sW4[idx] = src[(size_t)(g * K_U + u0g + w) * 256 + i];
    }
    // ---- stage biases: sBias[layer][u][4] = {bz, br, bi, bh} ----
    if (tid < 32) {
        int layer = tid >> 4, u = (tid >> 2) & 3, q = tid & 3;
        const float* bb = layer ? b1 : b0;
        int uu = u0g + u;
        float v;
        if (q == 0)      v = bb[uu] + bb[K_G3 + uu];
        else if (q == 1) v = bb[K_U + uu] + bb[K_G3 + K_U + uu];
        else if (q == 2) v = bb[2 * K_U + uu];
        else             v = bb[K_G3 + 2 * K_U + uu];
        sts32(sbase + BIAS_OFF + (unsigned)tid * 4u, v);
    }
    // ---- stage mask as bit-words: smask[b*16 + w] covers t in [32w, 32w+32) ----
    for (int wg = kh; wg < 1024; wg += 16) {
        int b = wg >> 4, w = wg & 15;
        int mv = mask[(size_t)b * K_T + w * 32 + lane];
        unsigned word = __ballot_sync(0xffffffffu, mv != 0);
        if (lane == 0)
            *reinterpret_cast<unsigned*>(smem + MASK_OFF + wg * 4) = word;
    }
    __syncthreads();

    const uint32_t rbase = sbase + RED_OFF;

    // finish roles: tid 0..127 => A-fin (b = tid>>1, half = tid&1); tid 128..255 => B-fin
    const int fth   = (tid < 128) ? tid : tid - 128;
    const int fb    = fth >> 1;
    const int fhalf = fth & 1;

    float2 h0v = make_float2(0.f, 0.f);     // A-fin threads
    float2 h1v = make_float2(0.f, 0.f);     // B-fin threads
    float2 prevv = make_float2(0.f, 0.f);
    const int sidx4 = cta * 64;

    for (int r = 0; r <= K_T; ++r) {
        const int p = r & 1, pb = p ^ 1;
        uint64_t acc[24];
#pragma unroll
        for (int i = 0; i < 24; ++i) acc[i] = 0;

        // ======== dots: A(r) on warps 0-7, B(r-1) on warps 8-15 ========
        if (kh < 8) {
            if (r < K_T) {
                const char* vp = (kh < 4)
                    ? (const char*)g_xT + (size_t)r * 131072 + (size_t)kh * 32768
                      + (size_t)lane * 16
                    : (const char*)g_h0 + (size_t)p * 131072 + (size_t)(kh - 4) * 32768
                      + (size_t)lane * 16;
                const uint32_t wb = (kh < 4) ? (sbase + (uint32_t)kh * 512u)
                                             : (sbase + 2048u + (uint32_t)(kh - 4) * 512u);
                dot32(vp, wb, acc);
                write_partials(rbase, lane, kh, acc);
            }
        } else {
            if (r >= 1) {
                const int kb = kh - 8;
                const char* vp = (kb < 4)
                    ? (const char*)g_h0n + (size_t)pb * 131072 + (size_t)kb * 32768
                      + (size_t)lane * 16
                    : (const char*)g_h1 + (size_t)pb * 131072 + (size_t)(kb - 4) * 32768
                      + (size_t)lane * 16;
                const uint32_t wb = (kb < 4) ? (sbase + 49152u + (uint32_t)kb * 512u)
                                             : (sbase + 51200u + (uint32_t)(kb - 4) * 512u);
                dot32(vp, wb, acc);
                write_partials(rbase, lane, kh, acc);
            }
        }
        __syncthreads();

        // ======== finish: A-fin(r) tid<128, B-fin(r-1) tid 128..255 ========
        if (tid < 128) {
            if (r < K_T) {
                float lo[6], hi[6];
#pragma unroll
                for (int jj = 0; jj < 6; ++jj) { lo[jj] = 0.f; hi[jj] = 0.f; }
#pragma unroll
                for (int kk = 0; kk < 4; ++kk)
#pragma unroll
                    for (int jj = 0; jj < 6; ++jj) {
                        const int j = (jj & 1) + (jj >> 1) * 4 + fhalf * 2;
                        lo[jj] += lds32(rbase + (unsigned)(((kk * 12 + j) * 64 + fb) * 4));
                        hi[jj] += lds32(rbase + (unsigned)((((kk + 4) * 12 + j) * 64 + fb) * 4));
                    }
                unsigned word = ldsu32(sbase + MASK_OFF + (unsigned)((fb * 16 + (r >> 5)) * 4));
                const bool m = (word >> (r & 31)) & 1u;
                float2 h0n2;
#pragma unroll
                for (int ul = 0; ul < 2; ++ul) {
                    const int u = fhalf * 2 + ul;
                    float bz = lds32(sbase + BIAS_OFF + (unsigned)((u * 4 + 0) * 4));
                    float br = lds32(sbase + BIAS_OFF + (unsigned)((u * 4 + 1) * 4));
                    float bi = lds32(sbase + BIAS_OFF + (unsigned)((u * 4 + 2) * 4));
                    float bh = lds32(sbase + BIAS_OFF + (unsigned)((u * 4 + 3) * 4));
                    float z    = sigmoid_f(lo[ul] + hi[ul] + bz);
                    float rr   = sigmoid_f(lo[2 + ul] + hi[2 + ul] + br);
                    float cand = tanhf(lo[4 + ul] + bi + rr * (hi[4 + ul] + bh));
                    float hp   = (ul == 0) ? h0v.x : h0v.y;
                    float h0n  = z * hp + (1.f - z) * cand;
                    if (ul == 0) { h0n2.x = h0n; h0v.x = m ? h0n : hp; }
                    else         { h0n2.y = h0n; h0v.y = m ? h0n : hp; }
                }
                reinterpret_cast<float2*>(g_h0n)[(p * 8192 + sidx4 + fb) * 2 + fhalf] = h0n2;
                reinterpret_cast<float2*>(g_h0)[((p ^ 1) * 8192 + sidx4 + fb) * 2 + fhalf] = h0v;
            }
        } else if (tid < 256) {
            if (r >= 1) {
                const int t = r - 1;
                float lo[6], hi[6];
#pragma unroll
                for (int jj = 0; jj < 6; ++jj) { lo[jj] = 0.f; hi[jj] = 0.f; }
#pragma unroll
                for (int kk = 0; kk < 4; ++kk)
#pragma unroll
                    for (int jj = 0; jj < 6; ++jj) {
                        const int j = (jj & 1) + (jj >> 1) * 4 + fhalf * 2;
                        lo[jj] += lds32(rbase + (unsigned)((((kk + 8) * 12 + j) * 64 + fb) * 4));
                        hi[jj] += lds32(rbase + (unsigned)((((kk + 12) * 12 + j) * 64 + fb) * 4));
                    }
                unsigned word = ldsu32(sbase + MASK_OFF + (unsigned)((fb * 16 + (t >> 5)) * 4));
                const bool m = (word >> (t & 31)) & 1u;
#pragma unroll
                for (int ul = 0; ul < 2; ++ul) {
                    const int u = fhalf * 2 + ul;
                    float bz = lds32(sbase + BIAS_OFF + (unsigned)((16 + u * 4 + 0) * 4));
                    float br = lds32(sbase + BIAS_OFF + (unsigned)((16 + u * 4 + 1) * 4));
                    float bi = lds32(sbase + BIAS_OFF + (unsigned)((16 + u * 4 + 2) * 4));
                    float bh = lds32(sbase + BIAS_OFF + (unsigned)((16 + u * 4 + 3) * 4));
                    float z    = sigmoid_f(lo[ul] + hi[ul] + bz);
                    float rr   = sigmoid_f(lo[2 + ul] + hi[2 + ul] + br);
                    float cand = tanhf(lo[4 + ul] + bi + rr * (hi[4 + ul] + bh));
                    float hp   = (ul == 0) ? h1v.x : h1v.y;
                    float h1n  = z * hp + (1.f - z) * cand;
                    if (ul == 0) { h1v.x = m ? h1n : hp; prevv.x = m ? h1n : prevv.x; }
                    else         { h1v.y = m ? h1n : hp; prevv.y = m ? h1n : prevv.y; }
                }
                reinterpret_cast<float2*>(g_h1)[(p * 8192 + sidx4 + fb) * 2 + fhalf] = h1v;
                reinterpret_cast<float2*>(out)[((size_t)fb * K_T + t) * 256 + cta * 2 + fhalf]
                    = prevv;
            }
        }

        if (r < K_T) grid_barrier((unsigned)(r + 1));
    }

    // finals: (output, h0f, h1f) in d_out (float2 units)
    const size_t fin2 = (size_t)K_B * K_T * 256;
    if (tid < 128)
        reinterpret_cast<float2*>(out)[fin2 + (size_t)fb * 256 + cta * 2 + fhalf] = h0v;
    else if (tid < 256)
        reinterpret_cast<float2*>(out)[fin2 + 64 * 256 + (size_t)fb * 256 + cta * 2 + fhalf] = h1v;
}

// ---------------- launch ----------------
extern "C" void kernel_launch(void* const* d_in, const int* in_sizes, int n_in,
                              void* d_out, int out_size) {
    (void)in_sizes; (void)n_in; (void)out_size;
    const float* x    = (const float*)d_in[0];
    const int*   mask = (const int*)d_in[1];
    const float* W0   = (const float*)d_in[2];
    const float* U0   = (const float*)d_in[3];
    const float* b0   = (const float*)d_in[4];
    const float* W1   = (const float*)d_in[5];
    const float* U1   = (const float*)d_in[6];
    const float* b1   = (const float*)d_in[7];
    float*       out  = (float*)d_out;

    cudaFuncSetAttribute(gru_main, cudaFuncAttributeMaxDynamicSharedMemorySize, SMEM_TOTAL);

    gru_init<<<(2 * K_B * K_U + 255) / 256, 256>>>();
    gru_pack_weights<<<(3 * K_U * 1024 + 255) / 256, 256>>>(W0, U0, W1, U1);
    {
        size_t n4 = (size_t)K_T * 128 * K_B;
        gru_transpose_x<<<(unsigned)((n4 + 255) / 256), 256>>>(x);
    }
    gru_main<<<N_CTA, N_THR, SMEM_TOTAL>>>(mask, b0, b1, out);
}